// round 1
// baseline (speedup 1.0000x reference)
#include <cuda_runtime.h>
#include <cuda_bf16.h>

#define B 2
#define S 2048
#define E 1024
#define H 16
#define D 64
#define BH (B*H)            // 32
#define NROW (B*S*H)        // 65536

// Scratch (allocation-free rule: __device__ globals)
__device__ float g_q[B*H*S*D];
__device__ float g_k[B*H*S*D];
__device__ float g_v[B*H*S*D];
__device__ float g_att[B*S*E];

#define PAD 68  // floats per shared row (16B aligned, phase-optimal for tx+16j row access)

// =====================================================================
// Kernel 1: QKV projection.  x viewed as 65536 rows of 64 (b,s,h order).
// q[b,h,s,e] = sum_d x[b,s,h*64+d] * Wq[e][d]   (torch Linear: x @ W^T)
// =====================================================================
#define K1_ROWS 16
#define QKV_SMEM ((3*64*PAD + K1_ROWS*64) * 4)

__global__ void __launch_bounds__(256) qkv_kernel(const float* __restrict__ x,
                                                  const float* __restrict__ Wq,
                                                  const float* __restrict__ Wk,
                                                  const float* __restrict__ Wv) {
    extern __shared__ float sm[];
    float* sWq = sm;
    float* sWk = sWq + 64*PAD;
    float* sWv = sWk + 64*PAD;
    float* sX  = sWv + 64*PAD;       // [16][64]

    const int tid = threadIdx.x;
    const int r   = tid >> 4;        // row within block (0..15)
    const int c   = tid & 15;        // output-lane (0..15)

    // Load weights into padded shared (rows = e, cols = k)
    for (int i = tid; i < 1024; i += 256) {
        int e = i >> 4, k4 = (i & 15) << 2;
        *(float4*)(sWq + e*PAD + k4) = *(const float4*)(Wq + e*64 + k4);
        *(float4*)(sWk + e*PAD + k4) = *(const float4*)(Wk + e*64 + k4);
        *(float4*)(sWv + e*PAD + k4) = *(const float4*)(Wv + e*64 + k4);
    }
    const int g0 = blockIdx.x * K1_ROWS;
    {
        int rr = tid >> 4, k4 = (tid & 15) << 2;
        *(float4*)(sX + rr*64 + k4) = *(const float4*)(x + (size_t)(g0 + rr)*64 + k4);
    }
    __syncthreads();

    float aq[4] = {0,0,0,0}, ak[4] = {0,0,0,0}, av[4] = {0,0,0,0};
    #pragma unroll 4
    for (int kk = 0; kk < 64; kk += 4) {
        float4 xv = *(const float4*)(sX + r*64 + kk);
        #pragma unroll
        for (int j = 0; j < 4; j++) {
            int e = c + 16*j;
            float4 wq = *(const float4*)(sWq + e*PAD + kk);
            float4 wk = *(const float4*)(sWk + e*PAD + kk);
            float4 wv = *(const float4*)(sWv + e*PAD + kk);
            aq[j] += xv.x*wq.x + xv.y*wq.y + xv.z*wq.z + xv.w*wq.w;
            ak[j] += xv.x*wk.x + xv.y*wk.y + xv.z*wk.z + xv.w*wk.w;
            av[j] += xv.x*wv.x + xv.y*wv.y + xv.z*wv.z + xv.w*wv.w;
        }
    }

    // Map row g -> (b,s,h); output layout (b,h,s,d)
    int g   = g0 + r;
    int b   = g >> 15;        // / (S*H) = 32768
    int rem = g & 32767;
    int s   = rem >> 4;       // / H
    int h   = rem & 15;
    size_t orow = ((size_t)(b*H + h)*S + s) * 64;
    #pragma unroll
    for (int j = 0; j < 4; j++) {
        int e = c + 16*j;
        g_q[orow + e] = aq[j];
        g_k[orow + e] = ak[j];
        g_v[orow + e] = av[j];
    }
}

// =====================================================================
// Kernel 2: flash attention, fp32.  Br = Bc = 64, D = 64.
// grid (S/64, B*H), block 256 (logical 16x16, 4x4 register micro-tile)
// =====================================================================
#define ATTN_SMEM (4*64*PAD*4)

__global__ void __launch_bounds__(256) attn_kernel() {
    extern __shared__ float sm[];
    float* sQ = sm;
    float* sK = sQ + 64*PAD;
    float* sV = sK + 64*PAD;
    float* sP = sV + 64*PAD;

    const int tid = threadIdx.x;
    const int tx  = tid & 15;
    const int ty  = tid >> 4;
    const int qt  = blockIdx.x;
    const int bh  = blockIdx.y;

    const float* Qg = g_q + (size_t)bh*S*D + (size_t)qt*64*D;
    const float* Kg = g_k + (size_t)bh*S*D;
    const float* Vg = g_v + (size_t)bh*S*D;

    // Load Q tile (64x64) once
    for (int i = tid; i < 1024; i += 256) {
        int r = i >> 4, c4 = (i & 15) << 2;
        *(float4*)(sQ + r*PAD + c4) = *(const float4*)(Qg + r*64 + c4);
    }

    float m[4], l[4], o[4][4];
    #pragma unroll
    for (int i = 0; i < 4; i++) {
        m[i] = -1e30f; l[i] = 0.f;
        #pragma unroll
        for (int j = 0; j < 4; j++) o[i][j] = 0.f;
    }

    const float scale = 0.125f;  // 1/sqrt(64)

    for (int kt = 0; kt < S/64; kt++) {
        __syncthreads();  // previous PV done (and first-iter Q load ordering w/ 2nd sync)
        const float* Kt = Kg + (size_t)kt*64*64;
        const float* Vt = Vg + (size_t)kt*64*64;
        for (int i = tid; i < 1024; i += 256) {
            int r = i >> 4, c4 = (i & 15) << 2;
            *(float4*)(sK + r*PAD + c4) = *(const float4*)(Kt + r*64 + c4);
            *(float4*)(sV + r*PAD + c4) = *(const float4*)(Vt + r*64 + c4);
        }
        __syncthreads();

        // S = Q K^T : thread owns q-rows 4ty+i, k-cols tx+16j
        float sc[4][4];
        #pragma unroll
        for (int i = 0; i < 4; i++)
            #pragma unroll
            for (int j = 0; j < 4; j++) sc[i][j] = 0.f;

        #pragma unroll 2
        for (int kk = 0; kk < 64; kk += 4) {
            float4 qv[4], kv[4];
            #pragma unroll
            for (int i = 0; i < 4; i++) qv[i] = *(const float4*)(sQ + (4*ty+i)*PAD + kk);
            #pragma unroll
            for (int j = 0; j < 4; j++) kv[j] = *(const float4*)(sK + (tx+16*j)*PAD + kk);
            #pragma unroll
            for (int i = 0; i < 4; i++)
                #pragma unroll
                for (int j = 0; j < 4; j++)
                    sc[i][j] += qv[i].x*kv[j].x + qv[i].y*kv[j].y +
                                qv[i].z*kv[j].z + qv[i].w*kv[j].w;
        }

        // Online softmax update per row (reduce across tx within warp halves)
        #pragma unroll
        for (int i = 0; i < 4; i++) {
            float rmax = fmaxf(fmaxf(sc[i][0], sc[i][1]), fmaxf(sc[i][2], sc[i][3]));
            #pragma unroll
            for (int msk = 8; msk >= 1; msk >>= 1)
                rmax = fmaxf(rmax, __shfl_xor_sync(0xffffffffu, rmax, msk));
            float mn   = fmaxf(m[i], rmax);
            float corr = __expf((m[i] - mn) * scale);
            m[i] = mn;
            float rs = 0.f;
            #pragma unroll
            for (int j = 0; j < 4; j++) {
                float p = __expf((sc[i][j] - mn) * scale);
                sP[(4*ty+i)*PAD + tx + 16*j] = p;
                rs += p;
            }
            #pragma unroll
            for (int msk = 8; msk >= 1; msk >>= 1)
                rs += __shfl_xor_sync(0xffffffffu, rs, msk);
            l[i] = l[i]*corr + rs;
            #pragma unroll
            for (int j = 0; j < 4; j++) o[i][j] *= corr;
        }
        __syncthreads();

        // O += P V : thread owns rows 4ty+i, d-cols 4tx+j
        #pragma unroll 2
        for (int cc = 0; cc < 64; cc += 4) {
            float4 pv[4], vv[4];
            #pragma unroll
            for (int i = 0; i < 4; i++) pv[i] = *(const float4*)(sP + (4*ty+i)*PAD + cc);
            #pragma unroll
            for (int c2 = 0; c2 < 4; c2++) vv[c2] = *(const float4*)(sV + (cc+c2)*PAD + 4*tx);
            #pragma unroll
            for (int i = 0; i < 4; i++) {
                float p0 = pv[i].x, p1 = pv[i].y, p2 = pv[i].z, p3 = pv[i].w;
                o[i][0] += p0*vv[0].x + p1*vv[1].x + p2*vv[2].x + p3*vv[3].x;
                o[i][1] += p0*vv[0].y + p1*vv[1].y + p2*vv[2].y + p3*vv[3].y;
                o[i][2] += p0*vv[0].z + p1*vv[1].z + p2*vv[2].z + p3*vv[3].z;
                o[i][3] += p0*vv[0].w + p1*vv[1].w + p2*vv[2].w + p3*vv[3].w;
            }
        }
    }

    // Epilogue: normalize & write in (b, s, e) layout
    const int b = bh >> 4, h = bh & 15;
    #pragma unroll
    for (int i = 0; i < 4; i++) {
        int srow = qt*64 + 4*ty + i;
        float inv = 1.0f / l[i];
        float4 val = make_float4(o[i][0]*inv, o[i][1]*inv, o[i][2]*inv, o[i][3]*inv);
        *(float4*)(g_att + ((size_t)(b*S + srow))*E + h*64 + 4*tx) = val;
    }
}

// =====================================================================
// Kernel 3: output projection  out = A @ Wo^T + bo  (A = g_att, 4096x1024)
// grid (E/64, (B*S)/64), block 256, 64x64 tiles, K loop over 1024
// =====================================================================
__global__ void __launch_bounds__(256) oproj_kernel(const float* __restrict__ Wo,
                                                    const float* __restrict__ bo,
                                                    float* __restrict__ out) {
    __shared__ float sA[64*PAD];
    __shared__ float sW[64*PAD];
    const int tid = threadIdx.x;
    const int tx  = tid & 15;
    const int ty  = tid >> 4;
    const int e0  = blockIdx.x * 64;
    const int m0  = blockIdx.y * 64;

    float acc[4][4];
    #pragma unroll
    for (int i = 0; i < 4; i++)
        #pragma unroll
        for (int j = 0; j < 4; j++) acc[i][j] = 0.f;

    for (int kc = 0; kc < E; kc += 64) {
        __syncthreads();
        for (int i = tid; i < 1024; i += 256) {
            int r = i >> 4, c4 = (i & 15) << 2;
            *(float4*)(sA + r*PAD + c4) = *(const float4*)(g_att + (size_t)(m0+r)*E + kc + c4);
            *(float4*)(sW + r*PAD + c4) = *(const float4*)(Wo   + (size_t)(e0+r)*E + kc + c4);
        }
        __syncthreads();

        #pragma unroll 2
        for (int kk = 0; kk < 64; kk += 4) {
            float4 av[4], wv[4];
            #pragma unroll
            for (int i = 0; i < 4; i++) av[i] = *(const float4*)(sA + (4*ty+i)*PAD + kk);
            #pragma unroll
            for (int j = 0; j < 4; j++) wv[j] = *(const float4*)(sW + (tx+16*j)*PAD + kk);
            #pragma unroll
            for (int i = 0; i < 4; i++)
                #pragma unroll
                for (int j = 0; j < 4; j++)
                    acc[i][j] += av[i].x*wv[j].x + av[i].y*wv[j].y +
                                 av[i].z*wv[j].z + av[i].w*wv[j].w;
        }
    }

    float bb[4];
    #pragma unroll
    for (int j = 0; j < 4; j++) bb[j] = bo[e0 + tx + 16*j];
    #pragma unroll
    for (int i = 0; i < 4; i++)
        #pragma unroll
        for (int j = 0; j < 4; j++)
            out[(size_t)(m0 + 4*ty + i)*E + e0 + tx + 16*j] = acc[i][j] + bb[j];
}

// =====================================================================
extern "C" void kernel_launch(void* const* d_in, const int* in_sizes, int n_in,
                              void* d_out, int out_size) {
    const float* x  = (const float*)d_in[0];
    const float* Wq = (const float*)d_in[1];
    const float* Wk = (const float*)d_in[2];
    const float* Wv = (const float*)d_in[3];
    const float* Wo = (const float*)d_in[4];
    const float* bo = (const float*)d_in[5];
    float* out = (float*)d_out;

    // Idempotent, deterministic, not stream ops (capture-safe). Called every time.
    cudaFuncSetAttribute(qkv_kernel,  cudaFuncAttributeMaxDynamicSharedMemorySize, QKV_SMEM);
    cudaFuncSetAttribute(attn_kernel, cudaFuncAttributeMaxDynamicSharedMemorySize, ATTN_SMEM);

    qkv_kernel<<<NROW / K1_ROWS, 256, QKV_SMEM>>>(x, Wq, Wk, Wv);
    attn_kernel<<<dim3(S/64, BH), 256, ATTN_SMEM>>>();
    oproj_kernel<<<dim3(E/64, (B*S)/64), 256>>>(Wo, bo, out);
}